// round 1
// baseline (speedup 1.0000x reference)
#include <cuda_runtime.h>

#define BB 32
#define TT 512
#define DD 384
#define D4 96
#define OT 8
#define THREADS 384
#define NW 12

// Scratch (no allocations allowed in kernel_launch)
__device__ float g_c[BB * TT];       // gaussian centers
__device__ float g_rinv[BB * TT];    // 1/(rng+1e-6)
__device__ float g_colsum[BB * DD];  // per-batch column sums of feats

// ---------------------------------------------------------------------------
// Prep: per-batch inclusive cumsum of durations -> centers; reciprocal widths
// ---------------------------------------------------------------------------
__global__ __launch_bounds__(TT) void prep_kernel(const float* __restrict__ rng,
                                                  const int* __restrict__ dur) {
    int b = blockIdx.x, t = threadIdx.x;
    __shared__ float s[TT];
    float d = (float)dur[b * TT + t];
    s[t] = d;
    __syncthreads();
    // Hillis-Steele inclusive scan (values are small ints -> fp32 exact)
    for (int off = 1; off < TT; off <<= 1) {
        float v = s[t];
        float add = (t >= off) ? s[t - off] : 0.0f;
        __syncthreads();
        s[t] = v + add;
        __syncthreads();
    }
    g_c[b * TT + t] = 0.5f * d + s[t];
    g_rinv[b * TT + t] = 1.0f / (rng[b * TT + t] + 1e-6f);
}

// ---------------------------------------------------------------------------
// Per-batch column sums of feats (exact handling of the 1e-6 weight floor)
// ---------------------------------------------------------------------------
__global__ __launch_bounds__(DD) void colsum_kernel(const float* __restrict__ feats) {
    int b = blockIdx.x, d = threadIdx.x;
    const float* fp = feats + (size_t)b * TT * DD + d;
    float acc = 0.0f;
    for (int t = 0; t < TT; t++) acc += fp[(size_t)t * DD];
    g_colsum[b * DD + d] = acc;
}

// ---------------------------------------------------------------------------
// Main: one block per (batch, tile of OT=8 output frames).
// Phase 1: compute 8x512 gaussian weights + exact per-output sums in smem,
//          plus the union token window where any weight > 1e-11.
// Phase 2: windowed matmul with float4 feats loads; 4 replicas x 2 outputs.
// ---------------------------------------------------------------------------
__global__ __launch_bounds__(THREADS) void upsample_kernel(const float* __restrict__ feats,
                                                           float* __restrict__ out,
                                                           int outlen) {
    int b = blockIdx.y;
    int o0 = blockIdx.x * OT;
    int tid = threadIdx.x;

    __shared__ float g[OT][TT];       // 16 KB
    __shared__ float invS[OT];
    __shared__ float wsum[NW][OT];
    __shared__ int sLo, sHi;
    if (tid == 0) { sLo = TT; sHi = -1; }
    __syncthreads();

    float psum[OT];
#pragma unroll
    for (int i = 0; i < OT; i++) psum[i] = 0.0f;
    int llo = TT, lhi = -1;

    for (int t = tid; t < TT; t += THREADS) {
        float c = g_c[b * TT + t];
        float ri = g_rinv[b * TT + t];
        float pref = ri * 0.3989422804014327f;  // 1/sqrt(2*pi) * 1/r
        bool keep = false;
#pragma unroll
        for (int i = 0; i < OT; i++) {
            float z = ((float)(o0 + i) - c) * ri;
            float gg = __expf(-0.5f * z * z) * pref;
            g[i][t] = gg;
            psum[i] += gg;
            keep |= (gg > 1e-11f);
        }
        if (keep) { llo = min(llo, t); lhi = max(lhi, t); }
    }
    if (lhi >= 0) { atomicMin(&sLo, llo); atomicMax(&sHi, lhi); }

    // Deterministic reduction of per-output weight sums
#pragma unroll
    for (int off = 16; off > 0; off >>= 1) {
#pragma unroll
        for (int i = 0; i < OT; i++)
            psum[i] += __shfl_down_sync(0xffffffffu, psum[i], off);
    }
    int w = tid >> 5, lane = tid & 31;
    if (lane == 0) {
#pragma unroll
        for (int i = 0; i < OT; i++) wsum[w][i] = psum[i];
    }
    __syncthreads();
    if (tid == 0) {
#pragma unroll
        for (int i = 0; i < OT; i++) {
            float S = (float)TT * 1e-6f;  // uniform floor contribution to sum
            for (int ww = 0; ww < NW; ww++) S += wsum[ww][i];
            invS[i] = 1.0f / S;
        }
    }
    __syncthreads();

    // Phase 2: windowed matmul
    int v = tid % D4;        // float4 column index (0..95)
    int rep = tid / D4;      // 0..3 -> outputs {2*rep, 2*rep+1}
    int i0 = rep * 2, i1 = i0 + 1;

    const float4* f4 = (const float4*)feats + (size_t)b * TT * D4 + v;
    float4 cs = ((const float4*)g_colsum)[b * D4 + v];
    float4 a0, a1;
    a0.x = cs.x * 1e-6f; a0.y = cs.y * 1e-6f; a0.z = cs.z * 1e-6f; a0.w = cs.w * 1e-6f;
    a1 = a0;

    int lo = sLo, hi = sHi;
    for (int t = lo; t <= hi; t++) {
        float4 f = f4[(size_t)t * D4];
        float g0 = g[i0][t];
        float g1 = g[i1][t];
        a0.x += g0 * f.x; a0.y += g0 * f.y; a0.z += g0 * f.z; a0.w += g0 * f.w;
        a1.x += g1 * f.x; a1.y += g1 * f.y; a1.z += g1 * f.z; a1.w += g1 * f.w;
    }

    float4* out4 = (float4*)out;
    int o = o0 + i0;
    if (o < outlen) {
        float s = invS[i0];
        float4 r;
        r.x = a0.x * s; r.y = a0.y * s; r.z = a0.z * s; r.w = a0.w * s;
        out4[((size_t)b * outlen + o) * D4 + v] = r;
    }
    if (o + 1 < outlen) {
        float s = invS[i1];
        float4 r;
        r.x = a1.x * s; r.y = a1.y * s; r.z = a1.z * s; r.w = a1.w * s;
        out4[((size_t)b * outlen + o + 1) * D4 + v] = r;
    }
}

extern "C" void kernel_launch(void* const* d_in, const int* in_sizes, int n_in,
                              void* d_out, int out_size) {
    const float* feats = (const float*)d_in[0];
    const float* rng = (const float*)d_in[1];
    const int* dur = (const int*)d_in[2];
    float* out = (float*)d_out;

    int outlen = out_size / (BB * DD);

    prep_kernel<<<BB, TT>>>(rng, dur);
    colsum_kernel<<<BB, DD>>>(feats);

    dim3 grid((outlen + OT - 1) / OT, BB);
    upsample_kernel<<<grid, THREADS>>>(feats, out, outlen);
}

// round 2
// speedup vs baseline: 1.2471x; 1.2471x over previous
#include <cuda_runtime.h>

#define BB 32
#define TT 512
#define DD 384
#define D4 96
#define OT 8
#define THREADS 384
#define WMAX 96
#define MAXTILES 1024
#define NCHUNK 8
#define MARGIN 30.0f

// Scratch (__device__ globals: no allocations allowed)
__device__ float g_c[BB * TT];               // gaussian centers (monotone per batch)
__device__ float g_rinv[BB * TT];            // 1/(rng+1e-6)
__device__ float4 g_colpart[NCHUNK][BB * D4];// partial column sums
__device__ float4 g_colsum[BB * D4];         // per-batch column sums of feats
__device__ int2 g_win[BB * MAXTILES];        // [lo_token, hi_token] per output tile

// ---------------------------------------------------------------------------
// Prep: per-batch inclusive cumsum of durations -> centers; reciprocal widths
// Warp scan + cross-warp scan (2 syncs total).
// ---------------------------------------------------------------------------
__global__ __launch_bounds__(TT) void prep_kernel(const float* __restrict__ rng,
                                                  const int* __restrict__ dur) {
    int b = blockIdx.x, t = threadIdx.x;
    int lane = t & 31, w = t >> 5;
    __shared__ float wtot[16];

    float d = (float)dur[b * TT + t];
    float x = d;
#pragma unroll
    for (int off = 1; off < 32; off <<= 1) {
        float y = __shfl_up_sync(0xffffffffu, x, off);
        if (lane >= off) x += y;
    }
    if (lane == 31) wtot[w] = x;
    __syncthreads();
    if (w == 0 && t < 16) {
        float v = wtot[t];
#pragma unroll
        for (int off = 1; off < 16; off <<= 1) {
            float y = __shfl_up_sync(0x0000ffffu, v, off);
            if (t >= off) v += y;
        }
        wtot[t] = v;
    }
    __syncthreads();
    float incl = x + (w > 0 ? wtot[w - 1] : 0.0f);
    g_c[b * TT + t] = 0.5f * d + incl;
    g_rinv[b * TT + t] = 1.0f / (rng[b * TT + t] + 1e-6f);
}

// ---------------------------------------------------------------------------
// Per-tile token windows: binary search on monotone centers (in smem).
// ---------------------------------------------------------------------------
__global__ __launch_bounds__(TT) void win_kernel(int ntiles) {
    __shared__ float c[TT];
    int b = blockIdx.x;
    c[threadIdx.x] = g_c[b * TT + threadIdx.x];
    __syncthreads();
    int ti = threadIdx.x;
    if (ti < ntiles) {
        float lob = (float)(ti * OT) - MARGIN;
        float hib = (float)(ti * OT + OT - 1) + MARGIN;
        int l = 0, r = TT;
        while (l < r) { int m = (l + r) >> 1; if (c[m] < lob) l = m + 1; else r = m; }
        int lo0 = l;
        l = 0; r = TT;
        while (l < r) { int m = (l + r) >> 1; if (c[m] <= hib) l = m + 1; else r = m; }
        int hi0 = l - 1;
        if (hi0 - lo0 + 1 > WMAX) hi0 = lo0 + WMAX - 1;  // safety (step>=1 => never)
        g_win[b * MAXTILES + ti] = make_int2(lo0, hi0);
    }
}

// ---------------------------------------------------------------------------
// Partial per-batch column sums (256 blocks to saturate DRAM on first touch)
// ---------------------------------------------------------------------------
__global__ __launch_bounds__(D4) void colsum_partial_kernel(const float* __restrict__ feats) {
    int b = blockIdx.x, k = blockIdx.y, v = threadIdx.x;
    const float4* f4 = (const float4*)feats + (size_t)b * TT * D4 + v;
    int t0 = k * (TT / NCHUNK);
    float4 acc = make_float4(0.f, 0.f, 0.f, 0.f);
    for (int t = t0; t < t0 + TT / NCHUNK; t++) {
        float4 f = f4[(size_t)t * D4];
        acc.x += f.x; acc.y += f.y; acc.z += f.z; acc.w += f.w;
    }
    g_colpart[k][b * D4 + v] = acc;
}

__global__ __launch_bounds__(THREADS) void colsum_combine_kernel() {
    int idx = blockIdx.x * THREADS + threadIdx.x;
    if (idx < BB * D4) {
        float4 acc = make_float4(0.f, 0.f, 0.f, 0.f);
#pragma unroll
        for (int k = 0; k < NCHUNK; k++) {
            float4 p = g_colpart[k][idx];
            acc.x += p.x; acc.y += p.y; acc.z += p.z; acc.w += p.w;
        }
        g_colsum[idx] = acc;
    }
}

// ---------------------------------------------------------------------------
// Main: one block per (batch, OT=8 output frames). Windowed weights + matmul.
// ---------------------------------------------------------------------------
__global__ __launch_bounds__(THREADS) void upsample_kernel(const float* __restrict__ feats,
                                                           float* __restrict__ out,
                                                           int outlen) {
    int b = blockIdx.y;
    int tile = blockIdx.x;
    int o0 = tile * OT;
    int tid = threadIdx.x;

    __shared__ float g[OT][WMAX];
    __shared__ float sInv[OT];
    __shared__ int sLo, sHi;

    int2 win = g_win[b * MAXTILES + tile];
    int lo0 = win.x;
    int width = win.y - win.x + 1;  // may be <= 0 (pure-floor region)

    if (tid == 0) { sLo = WMAX; sHi = -1; }
    __syncthreads();

    // Phase 1: gaussian weights on the candidate window only
    if (tid < width) {
        int t = lo0 + tid;
        float c = g_c[b * TT + t];
        float ri = g_rinv[b * TT + t];
        float pref = ri * 0.3989422804014327f;
        bool keep = false;
#pragma unroll
        for (int i = 0; i < OT; i++) {
            float z = ((float)(o0 + i) - c) * ri;
            float gg = __expf(-0.5f * z * z) * pref;
            g[i][tid] = gg;
            keep |= (gg > 1e-11f);
        }
        if (keep) { atomicMin(&sLo, tid); atomicMax(&sHi, tid); }
    }
    __syncthreads();

    // Per-output weight sums: warp i reduces row i (deterministic)
    int w = tid >> 5, lane = tid & 31;
    if (w < OT) {
        float s = 0.0f;
        for (int j = lane; j < width; j += 32) s += g[w][j];
#pragma unroll
        for (int off = 16; off > 0; off >>= 1)
            s += __shfl_down_sync(0xffffffffu, s, off);
        if (lane == 0) sInv[w] = 1.0f / (s + (float)TT * 1e-6f);
    }
    __syncthreads();

    // Phase 2: windowed rank-update matmul. 4 replicas x 2 outputs each.
    int v = tid % D4;
    int rep = tid / D4;
    int i0 = rep * 2, i1 = i0 + 1;

    float4 cs = g_colsum[b * D4 + v];
    float4 a0, a1;
    a0.x = cs.x * 1e-6f; a0.y = cs.y * 1e-6f; a0.z = cs.z * 1e-6f; a0.w = cs.w * 1e-6f;
    a1 = a0;

    const float4* f4 = (const float4*)feats + ((size_t)b * TT + lo0) * D4 + v;
    int jlo = sLo, jhi = sHi;
    for (int j = jlo; j <= jhi; j++) {
        float4 f = f4[(size_t)j * D4];
        float g0 = g[i0][j];
        float g1 = g[i1][j];
        a0.x += g0 * f.x; a0.y += g0 * f.y; a0.z += g0 * f.z; a0.w += g0 * f.w;
        a1.x += g1 * f.x; a1.y += g1 * f.y; a1.z += g1 * f.z; a1.w += g1 * f.w;
    }

    float4* out4 = (float4*)out;
    int o = o0 + i0;
    if (o < outlen) {
        float s = sInv[i0];
        float4 r;
        r.x = a0.x * s; r.y = a0.y * s; r.z = a0.z * s; r.w = a0.w * s;
        out4[((size_t)b * outlen + o) * D4 + v] = r;
    }
    if (o + 1 < outlen) {
        float s = sInv[i1];
        float4 r;
        r.x = a1.x * s; r.y = a1.y * s; r.z = a1.z * s; r.w = a1.w * s;
        out4[((size_t)b * outlen + o + 1) * D4 + v] = r;
    }
}

extern "C" void kernel_launch(void* const* d_in, const int* in_sizes, int n_in,
                              void* d_out, int out_size) {
    const float* feats = (const float*)d_in[0];
    const float* rng = (const float*)d_in[1];
    const int* dur = (const int*)d_in[2];
    float* out = (float*)d_out;

    int outlen = out_size / (BB * DD);
    int ntiles = (outlen + OT - 1) / OT;

    prep_kernel<<<BB, TT>>>(rng, dur);
    win_kernel<<<BB, TT>>>(ntiles);
    colsum_partial_kernel<<<dim3(BB, NCHUNK), D4>>>(feats);
    colsum_combine_kernel<<<(BB * D4 + THREADS - 1) / THREADS, THREADS>>>();
    upsample_kernel<<<dim3(ntiles, BB), THREADS>>>(feats, out, outlen);
}

// round 4
// speedup vs baseline: 1.2842x; 1.0297x over previous
#include <cuda_runtime.h>

#define BB 32
#define TT 512
#define DD 384
#define D4 96
#define OT 32
#define TUP 192            // upsample threads: 2 reps x 96 lanes
#define NOUT 16            // outputs per thread
#define WMAX 96
#define MAXTILES 128
#define MARGIN 30.0f

// Scratch (__device__ globals: no allocations allowed)
__device__ float g_c[BB * TT];      // gaussian centers (monotone per batch)
__device__ float g_rinv[BB * TT];   // 1/(rng+1e-6)
__device__ float4 g_colsum[BB * D4];
__device__ int2 g_win[BB * MAXTILES];

#define FMA2(acc, a, b) \
    asm("fma.rn.f32x2 %0, %1, %2, %0;" : "+l"(acc) : "l"(a), "l"(b))

// ---------------------------------------------------------------------------
// Kernel A (one block per batch): duration scan -> centers + rinv,
// per-tile token windows (binary search), per-batch feats column sums.
// ---------------------------------------------------------------------------
__global__ __launch_bounds__(TT) void prep_kernel(const float* __restrict__ feats,
                                                  const float* __restrict__ rng,
                                                  const int* __restrict__ dur,
                                                  int ntiles) {
    int b = blockIdx.x, t = threadIdx.x;
    int lane = t & 31, w = t >> 5;
    __shared__ float sc[TT];
    __shared__ float wtot[16];
    __shared__ float4 part[4][D4];

    // --- inclusive scan of durations ---
    float d = (float)dur[b * TT + t];
    float x = d;
#pragma unroll
    for (int off = 1; off < 32; off <<= 1) {
        float y = __shfl_up_sync(0xffffffffu, x, off);
        if (lane >= off) x += y;
    }
    if (lane == 31) wtot[w] = x;
    __syncthreads();
    if (w == 0 && t < 16) {
        float v = wtot[t];
#pragma unroll
        for (int off = 1; off < 16; off <<= 1) {
            float y = __shfl_up_sync(0x0000ffffu, v, off);
            if (t >= off) v += y;
        }
        wtot[t] = v;
    }
    __syncthreads();
    float c = 0.5f * d + x + (w > 0 ? wtot[w - 1] : 0.0f);
    sc[t] = c;
    g_c[b * TT + t] = c;
    g_rinv[b * TT + t] = 1.0f / (rng[b * TT + t] + 1e-6f);
    __syncthreads();

    // --- per-tile windows: binary search on monotone centers ---
    if (t < ntiles) {
        float lob = (float)(t * OT) - MARGIN;
        float hib = (float)(t * OT + OT - 1) + MARGIN;
        int l = 0, r = TT;
        while (l < r) { int m = (l + r) >> 1; if (sc[m] < lob) l = m + 1; else r = m; }
        int lo0 = l;
        l = 0; r = TT;
        while (l < r) { int m = (l + r) >> 1; if (sc[m] <= hib) l = m + 1; else r = m; }
        int hi0 = l - 1;
        if (hi0 - lo0 + 1 > WMAX) hi0 = lo0 + WMAX - 1;  // safety (step>=1 => never)
        g_win[b * MAXTILES + t] = make_int2(lo0, hi0);
    }

    // --- per-batch column sums (4 chunks x 128 rows), deterministic combine ---
    if (t < 384) {
        int v = t % D4, ch = t / D4;
        const float4* f4 = (const float4*)feats + ((size_t)b * TT + ch * 128) * D4 + v;
        float4 acc = make_float4(0.f, 0.f, 0.f, 0.f);
#pragma unroll 4
        for (int tt = 0; tt < 128; tt++) {
            float4 f = f4[(size_t)tt * D4];
            acc.x += f.x; acc.y += f.y; acc.z += f.z; acc.w += f.w;
        }
        part[ch][v] = acc;
    }
    __syncthreads();
    if (t < D4) {
        float4 acc = part[0][t];
#pragma unroll
        for (int ch = 1; ch < 4; ch++) {
            float4 p = part[ch][t];
            acc.x += p.x; acc.y += p.y; acc.z += p.z; acc.w += p.w;
        }
        g_colsum[b * D4 + t] = acc;
    }
}

// ---------------------------------------------------------------------------
// Main: one block per (batch, OT=32 output frames).
// Phase 1: gaussian weights on candidate window, stored as duplicated pairs.
// Phase 2: windowed matmul with packed f32x2 FMAs.
// ---------------------------------------------------------------------------
__global__ __launch_bounds__(TUP) void upsample_kernel(const float* __restrict__ feats,
                                                       float* __restrict__ out,
                                                       int outlen) {
    int b = blockIdx.y;
    int tile = blockIdx.x;
    int o0 = tile * OT;
    int tid = threadIdx.x;
    int lane = tid & 31, w = tid >> 5;

    __shared__ float gT2[WMAX * 2 * OT];  // [j][2*i] duplicated pairs, 24 KB
    __shared__ float ps[6][32];           // row-sum partials per warp-stripe
    __shared__ float sInv[OT];
    __shared__ float scc[WMAX], sri[WMAX];
    __shared__ int sLo, sHi;

    int2 win = g_win[b * MAXTILES + tile];
    int lo0 = win.x;
    int width = win.y - win.x + 1;  // may be <= 0 (pure-floor region)
    if (width < 0) width = 0;

    if (tid == 0) { sLo = WMAX; sHi = -1; }
    if (tid < width) {
        scc[tid] = g_c[b * TT + lo0 + tid];
        sri[tid] = g_rinv[b * TT + lo0 + tid];
    }
    __syncthreads();

    // Phase 1: weights over (j, i) grid
    int jmin = WMAX, jmax = -1;
    for (int idx = tid; idx < width * OT; idx += TUP) {
        int j = idx >> 5, i = idx & 31;
        float c = scc[j], ri = sri[j];
        float z = ((float)(o0 + i) - c) * ri;
        float gg = __expf(-0.5f * z * z) * (ri * 0.3989422804014327f);
        *(float2*)&gT2[j * (2 * OT) + 2 * i] = make_float2(gg, gg);
        if (gg > 1e-11f) { jmin = min(jmin, j); jmax = max(jmax, j); }
    }
    if (jmax >= 0) { atomicMin(&sLo, jmin); atomicMax(&sHi, jmax); }
    __syncthreads();   // gT2 fully written before row-sum reads (R3 bug: was missing)

    // Row sums: warp w covers j-stripe [16w, 16w+16); lane i accumulates row i.
    {
        float s = 0.0f;
        int j0 = w * 16, j1 = min(width, j0 + 16);
        for (int j = j0; j < j1; j++) s += gT2[j * (2 * OT) + 2 * lane];
        ps[w][lane] = s;
    }
    __syncthreads();
    if (tid < OT) {
        float s = (float)TT * 1e-6f;  // uniform floor mass
#pragma unroll
        for (int ww = 0; ww < 6; ww++) s += ps[ww][tid];
        sInv[tid] = 1.0f / s;
    }
    __syncthreads();

    // Phase 2: windowed matmul, packed f32x2
    int v = tid % D4;
    int rep = tid / D4;
    int ibase = rep * NOUT;

    float4 cs = g_colsum[b * D4 + v];
    unsigned long long A[NOUT][2];
    {
        float2 lo = make_float2(cs.x * 1e-6f, cs.y * 1e-6f);
        float2 hi = make_float2(cs.z * 1e-6f, cs.w * 1e-6f);
        unsigned long long l0 = *(unsigned long long*)&lo;
        unsigned long long h0 = *(unsigned long long*)&hi;
#pragma unroll
        for (int k = 0; k < NOUT; k++) { A[k][0] = l0; A[k][1] = h0; }
    }

    const ulonglong2* f2 = (const ulonglong2*)feats + ((size_t)b * TT + lo0) * D4 + v;
    int jlo = sLo, jhi = sHi;
    for (int j = jlo; j <= jhi; j++) {
        ulonglong2 f = f2[(size_t)j * D4];
        const float* grow = &gT2[j * (2 * OT) + 2 * ibase];
#pragma unroll
        for (int k = 0; k < NOUT; k += 2) {
            ulonglong2 gp = *(const ulonglong2*)(grow + 2 * k);
            FMA2(A[k][0], f.x, gp.x);
            FMA2(A[k][1], f.y, gp.x);
            FMA2(A[k + 1][0], f.x, gp.y);
            FMA2(A[k + 1][1], f.y, gp.y);
        }
    }

    // Epilogue: normalize + store
    float4* out4 = (float4*)out;
#pragma unroll
    for (int k = 0; k < NOUT; k++) {
        int o = o0 + ibase + k;
        if (o < outlen) {
            float s = sInv[ibase + k];
            unsigned long long a0 = A[k][0], a1 = A[k][1];
            float4 r;
            r.x = __uint_as_float((unsigned)(a0 & 0xffffffffu)) * s;
            r.y = __uint_as_float((unsigned)(a0 >> 32)) * s;
            r.z = __uint_as_float((unsigned)(a1 & 0xffffffffu)) * s;
            r.w = __uint_as_float((unsigned)(a1 >> 32)) * s;
            out4[((size_t)b * outlen + o) * D4 + v] = r;
        }
    }
}

extern "C" void kernel_launch(void* const* d_in, const int* in_sizes, int n_in,
                              void* d_out, int out_size) {
    const float* feats = (const float*)d_in[0];
    const float* rng = (const float*)d_in[1];
    const int* dur = (const int*)d_in[2];
    float* out = (float*)d_out;

    int outlen = out_size / (BB * DD);
    int ntiles = (outlen + OT - 1) / OT;

    prep_kernel<<<BB, TT>>>(feats, rng, dur, ntiles);
    upsample_kernel<<<dim3(ntiles, BB), TUP>>>(feats, out, outlen);
}

// round 5
// speedup vs baseline: 2.1376x; 1.6646x over previous
#include <cuda_runtime.h>

#define BB 32
#define TT 512
#define DD 384
#define D4 96
#define OT 16              // output frames per tile
#define TUP 192            // upsample threads: 2 reps x 96 lanes
#define NOUT 8             // outputs per thread
#define NP 4               // output pairs per thread
#define WMAX 96
#define MAXTILES 256
#define NCHUNK 8
#define MARGIN 30.0f

// Scratch (__device__ globals: no allocations allowed)
__device__ float g_c[BB * TT];                 // gaussian centers (monotone per batch)
__device__ float g_rinv[BB * TT];              // 1/(rng+1e-6)
__device__ float4 g_colpart[NCHUNK][BB * D4];  // partial feats column sums
__device__ int2 g_win[BB * MAXTILES];          // per-tile token windows

#define FMA2(acc, a, b) \
    asm("fma.rn.f32x2 %0, %1, %2, %0;" : "+l"(acc) : "l"(a), "l"(b))
#define DUP(dst, src) \
    asm("mov.b64 %0, {%1, %1};" : "=l"(dst) : "r"(src))

// ---------------------------------------------------------------------------
// Prep, grid (BB, NCHUNK): every block sums its 64-row feats chunk (partials);
// the ky==0 block additionally does the duration scan -> centers/rinv and the
// per-tile window binary searches.
// ---------------------------------------------------------------------------
__global__ __launch_bounds__(TT) void prep_kernel(const float* __restrict__ feats,
                                                  const float* __restrict__ rng,
                                                  const int* __restrict__ dur,
                                                  int ntiles) {
    int b = blockIdx.x, ky = blockIdx.y, t = threadIdx.x;
    int lane = t & 31, w = t >> 5;
    __shared__ float4 part[4][D4];
    __shared__ float sc[TT];
    __shared__ float wtot[16];

    // --- partial column sums: chunk ky = rows [ky*64, ky*64+64), 4 sub-slices ---
    if (t < 384) {
        int v = t % D4, sub = t / D4;
        const float4* f4 = (const float4*)feats + ((size_t)b * TT + ky * 64 + sub * 16) * D4 + v;
        float4 acc = make_float4(0.f, 0.f, 0.f, 0.f);
#pragma unroll
        for (int r = 0; r < 16; r++) {
            float4 f = f4[(size_t)r * D4];
            acc.x += f.x; acc.y += f.y; acc.z += f.z; acc.w += f.w;
        }
        part[sub][v] = acc;
    }
    __syncthreads();
    if (t < D4) {
        float4 acc = part[0][t];
#pragma unroll
        for (int s = 1; s < 4; s++) {
            float4 p = part[s][t];
            acc.x += p.x; acc.y += p.y; acc.z += p.z; acc.w += p.w;
        }
        g_colpart[ky][b * D4 + t] = acc;
    }

    if (ky != 0) return;

    // --- inclusive scan of durations -> centers ---
    float d = (float)dur[b * TT + t];
    float x = d;
#pragma unroll
    for (int off = 1; off < 32; off <<= 1) {
        float y = __shfl_up_sync(0xffffffffu, x, off);
        if (lane >= off) x += y;
    }
    if (lane == 31) wtot[w] = x;
    __syncthreads();
    if (w == 0 && t < 16) {
        float v = wtot[t];
#pragma unroll
        for (int off = 1; off < 16; off <<= 1) {
            float y = __shfl_up_sync(0x0000ffffu, v, off);
            if (t >= off) v += y;
        }
        wtot[t] = v;
    }
    __syncthreads();
    float c = 0.5f * d + x + (w > 0 ? wtot[w - 1] : 0.0f);
    sc[t] = c;
    g_c[b * TT + t] = c;
    g_rinv[b * TT + t] = 1.0f / (rng[b * TT + t] + 1e-6f);
    __syncthreads();

    // --- per-tile windows: binary search on monotone centers ---
    if (t < ntiles) {
        float lob = (float)(t * OT) - MARGIN;
        float hib = (float)(t * OT + OT - 1) + MARGIN;
        int l = 0, r = TT;
        while (l < r) { int m = (l + r) >> 1; if (sc[m] < lob) l = m + 1; else r = m; }
        int lo0 = l;
        l = 0; r = TT;
        while (l < r) { int m = (l + r) >> 1; if (sc[m] <= hib) l = m + 1; else r = m; }
        int hi0 = l - 1;
        if (hi0 - lo0 + 1 > WMAX) hi0 = lo0 + WMAX - 1;  // safety (step>=1 => never)
        g_win[b * MAXTILES + t] = make_int2(lo0, hi0);
    }
}

// ---------------------------------------------------------------------------
// Main: one block per (batch, OT=16 output frames).
// Phase 1: gaussian weights on candidate window (natural layout gT[j][i]).
// Phase 2: windowed matmul, f32x2 packed over OUTPUT pairs:
//   A[col][pair] += {f_col,f_col} * {g_2p, g_2p+1}
// so g pairs come straight from smem (2x LDS.128/j) and f is duplicated in
// registers (4x mov.b64/j). Next-j feats prefetch breaks the LDG dep chain.
// ---------------------------------------------------------------------------
__global__ __launch_bounds__(TUP, 5) void upsample_kernel(const float* __restrict__ feats,
                                                          float* __restrict__ out,
                                                          int outlen) {
    int b = blockIdx.y;
    int tile = blockIdx.x;
    int o0 = tile * OT;
    int tid = threadIdx.x;
    int lane = tid & 31, w = tid >> 5;

    __shared__ __align__(16) float gT[WMAX * OT];  // 6 KB
    __shared__ float ps[6][OT];
    __shared__ float sInv[OT];
    __shared__ float scc[WMAX], sri[WMAX];
    __shared__ int sLo, sHi;

    int2 win = g_win[b * MAXTILES + tile];
    int lo0 = win.x;
    int width = win.y - win.x + 1;  // may be <= 0 (pure-floor region)
    if (width < 0) width = 0;

    if (tid == 0) { sLo = WMAX; sHi = -1; }
    if (tid < width) {
        scc[tid] = g_c[b * TT + lo0 + tid];
        sri[tid] = g_rinv[b * TT + lo0 + tid];
    }
    __syncthreads();

    // Phase 1: weights over (j, i) grid
    int jmin = WMAX, jmax = -1;
    for (int idx = tid; idx < width * OT; idx += TUP) {
        int j = idx >> 4, i = idx & 15;
        float c = scc[j], ri = sri[j];
        float z = ((float)(o0 + i) - c) * ri;
        float gg = __expf(-0.5f * z * z) * (ri * 0.3989422804014327f);
        gT[idx] = gg;
        if (gg > 1e-11f) { jmin = min(jmin, j); jmax = max(jmax, j); }
    }
    if (jmax >= 0) { atomicMin(&sLo, jmin); atomicMax(&sHi, jmax); }
    __syncthreads();

    // Row sums: warp w covers j-stripe [16w, 16w+16); lane i < OT accumulates row i.
    if (lane < OT) {
        float s = 0.0f;
        int j0 = w * 16, j1 = min(width, j0 + 16);
        for (int j = j0; j < j1; j++) s += gT[j * OT + lane];
        ps[w][lane] = s;
    }
    __syncthreads();
    if (tid < OT) {
        float s = (float)TT * 1e-6f;  // uniform floor mass
#pragma unroll
        for (int ww = 0; ww < 6; ww++) s += ps[ww][tid];
        sInv[tid] = 1.0f / s;
    }
    __syncthreads();

    // Phase 2 setup
    int v = tid % D4;
    int rep = tid / D4;
    int ibase = rep * NOUT;

    // Combine colsum partials (L2-resident table)
    float4 cs = make_float4(0.f, 0.f, 0.f, 0.f);
#pragma unroll
    for (int kc = 0; kc < NCHUNK; kc++) {
        float4 p = g_colpart[kc][b * D4 + v];
        cs.x += p.x; cs.y += p.y; cs.z += p.z; cs.w += p.w;
    }

    unsigned long long A[4][NP];
    {
        unsigned long long d0, d1, d2, d3;
        DUP(d0, __float_as_uint(cs.x * 1e-6f));
        DUP(d1, __float_as_uint(cs.y * 1e-6f));
        DUP(d2, __float_as_uint(cs.z * 1e-6f));
        DUP(d3, __float_as_uint(cs.w * 1e-6f));
#pragma unroll
        for (int p = 0; p < NP; p++) { A[0][p] = d0; A[1][p] = d1; A[2][p] = d2; A[3][p] = d3; }
    }

    const uint4* f4 = (const uint4*)feats + ((size_t)b * TT + lo0) * D4 + v;
    int jlo = sLo, jhi = sHi;
    if (jlo <= jhi) {
        uint4 f = f4[(size_t)jlo * D4];
        for (int j = jlo; j <= jhi; j++) {
            int jn = (j < jhi) ? (j + 1) : jhi;     // clamped, branch-free prefetch
            uint4 fn = f4[(size_t)jn * D4];
            unsigned long long fd0, fd1, fd2, fd3;
            DUP(fd0, f.x); DUP(fd1, f.y); DUP(fd2, f.z); DUP(fd3, f.w);
            const ulonglong2* gp = (const ulonglong2*)&gT[j * OT + ibase];
            ulonglong2 gA = gp[0];
            ulonglong2 gB = gp[1];
            FMA2(A[0][0], fd0, gA.x); FMA2(A[1][0], fd1, gA.x);
            FMA2(A[2][0], fd2, gA.x); FMA2(A[3][0], fd3, gA.x);
            FMA2(A[0][1], fd0, gA.y); FMA2(A[1][1], fd1, gA.y);
            FMA2(A[2][1], fd2, gA.y); FMA2(A[3][1], fd3, gA.y);
            FMA2(A[0][2], fd0, gB.x); FMA2(A[1][2], fd1, gB.x);
            FMA2(A[2][2], fd2, gB.x); FMA2(A[3][2], fd3, gB.x);
            FMA2(A[0][3], fd0, gB.y); FMA2(A[1][3], fd1, gB.y);
            FMA2(A[2][3], fd2, gB.y); FMA2(A[3][3], fd3, gB.y);
            f = fn;
        }
    }

    // Epilogue: normalize + store (low halves = even output, high = odd)
    float4* out4 = (float4*)out;
#pragma unroll
    for (int p = 0; p < NP; p++) {
        int o = o0 + ibase + 2 * p;
        if (o < outlen) {
            float s = sInv[ibase + 2 * p];
            float4 r;
            r.x = __uint_as_float((unsigned)A[0][p]) * s;
            r.y = __uint_as_float((unsigned)A[1][p]) * s;
            r.z = __uint_as_float((unsigned)A[2][p]) * s;
            r.w = __uint_as_float((unsigned)A[3][p]) * s;
            out4[((size_t)b * outlen + o) * D4 + v] = r;
        }
        if (o + 1 < outlen) {
            float s = sInv[ibase + 2 * p + 1];
            float4 r;
            r.x = __uint_as_float((unsigned)(A[0][p] >> 32)) * s;
            r.y = __uint_as_float((unsigned)(A[1][p] >> 32)) * s;
            r.z = __uint_as_float((unsigned)(A[2][p] >> 32)) * s;
            r.w = __uint_as_float((unsigned)(A[3][p] >> 32)) * s;
            out4[((size_t)b * outlen + o + 1) * D4 + v] = r;
        }
    }
}

extern "C" void kernel_launch(void* const* d_in, const int* in_sizes, int n_in,
                              void* d_out, int out_size) {
    const float* feats = (const float*)d_in[0];
    const float* rng = (const float*)d_in[1];
    const int* dur = (const int*)d_in[2];
    float* out = (float*)d_out;

    int outlen = out_size / (BB * DD);
    int ntiles = (outlen + OT - 1) / OT;

    prep_kernel<<<dim3(BB, NCHUNK), TT>>>(feats, rng, dur, ntiles);
    upsample_kernel<<<dim3(ntiles, BB), TUP>>>(feats, out, outlen);
}